// round 5
// baseline (speedup 1.0000x reference)
#include <cuda_runtime.h>
#include <cuda_bf16.h>

// 3x3 PCF shadow visibility, 2 pixels per thread:
// vis = (1/9) * sum sigmoid((zbuf[b, clamp(y+ii), clamp(x+jj)] - (z - 0.008)) * 1000)

__device__ __forceinline__ float ex2f(float x) {
    float y; asm("ex2.approx.f32 %0, %1;" : "=f"(y) : "f"(x)); return y;
}
__device__ __forceinline__ float rcpf(float x) {
    float y; asm("rcp.approx.f32 %0, %1;" : "=f"(y) : "f"(x)); return y;
}

// p_i = 1 + exp2(min(u_i, 30)); sum of 1/p over a quad with one rcp.
__device__ __forceinline__ float quad_sum(float p0, float p1, float p2, float p3) {
    float a = p0 * p1;
    float b = p2 * p3;
    float num = (p0 + p1) * b + (p2 + p3) * a;
    return num * rcpf(a * b);
}
__device__ __forceinline__ float pval(float v, float C, float K) {
    float u = fmaf(-v, K, C);
    u = fminf(u, 30.0f);
    return 1.0f + ex2f(u);
}

__global__ __launch_bounds__(256, 8) void shadow_pcf2_kernel(
    const float* __restrict__ zbuf,       // [N, S, S]
    const float* __restrict__ depth,      // [N, H, W, K]
    const int*   __restrict__ xy,         // [N, H, W, K, 2]
    const int*   __restrict__ image_size, // scalar S (device)
    float*       __restrict__ out,        // [N, H, W, K]
    int total,                            // N*H*W*K
    int zbuf_total)                       // N*S*S
{
    __shared__ int sm_S, sm_b0, sm_lim;
    __shared__ unsigned sm_SS;

    const int i    = blockIdx.x * blockDim.x + threadIdx.x;
    const int idx0 = 2 * i;

    if (threadIdx.x == 0) {
        int S = *image_size;
        unsigned SS = (unsigned)S * (unsigned)S;
        int N   = (int)((unsigned)zbuf_total / SS);
        int HWK = total / N;
        int base = blockIdx.x * blockDim.x * 2;
        int b0 = base / HWK;
        sm_S = S; sm_SS = SS; sm_b0 = b0;
        sm_lim = (b0 + 1) * HWK;
    }
    __syncthreads();

    if (idx0 >= total) return;

    const int S       = sm_S;
    const unsigned SS = sm_SS;
    const int b0v     = sm_b0;
    const int lim     = sm_lim;
    const bool has2   = (idx0 + 1) < total;

    const float Kc = 1000.0f * 1.4426950408889634f;

    int xs[2], ys[2];
    float C_[2];
    if (has2) {
        int4   cc = __ldcs((const int4*)(xy + 2 * idx0));    // x0,y0,x1,y1 (read-once)
        float2 dd = __ldcs((const float2*)(depth + idx0));   // read-once
        xs[0] = cc.x; ys[0] = cc.y; xs[1] = cc.z; ys[1] = cc.w;
        C_[0] = (dd.x - 0.008f) * Kc;
        C_[1] = (dd.y - 0.008f) * Kc;
    } else {
        int2 cc = __ldcs((const int2*)(xy + 2 * idx0));
        xs[0] = cc.x; ys[0] = cc.y; xs[1] = 0; ys[1] = 0;
        C_[0] = (__ldcs(depth + idx0) - 0.008f) * Kc;
        C_[1] = 0.0f;
    }

    float acc[2] = {0.0f, 0.0f};

    if ((S & 3) == 0) {
        // ---- fast path: rows 16B-aligned ----
        const float* rows[2][3];
        bool d2_[2], d1_[2], lo_[2], hi_[2], nq_[2];

#pragma unroll
        for (int p = 0; p < 2; ++p) {
            const int idx = idx0 + p;
            const int b   = b0v + (idx >= lim);
            const int x = xs[p], y = ys[p];
            const int ym = max(y - 1, 0);
            const int yp = min(y + 1, S - 1);
            const int xi = min(max(x, 1), S - 2);
            const int c0 = xi - 1;
            const int e16 = c0 & ~3;
            const int d   = c0 - e16;          // 0..3
            nq_[p] = (d >= 2);
            d2_[p] = (d & 2) != 0;
            d1_[p] = (d & 1) != 0;
            lo_[p] = (x < 1);
            hi_[p] = (x > S - 2);
            const float* zb = zbuf + (size_t)b * (size_t)SS;
            rows[p][0] = zb + (size_t)(unsigned)ym * (unsigned)S + e16;
            rows[p][1] = zb + (size_t)(unsigned)y  * (unsigned)S + e16;
            rows[p][2] = zb + (size_t)(unsigned)yp * (unsigned)S + e16;
        }

        // Issue all gathers before any consumption (max MLP).
        float4 P[2][3];
        float2 Q[2][3];
#pragma unroll
        for (int p = 0; p < 2; ++p)
#pragma unroll
            for (int r = 0; r < 3; ++r)
                P[p][r] = __ldg((const float4*)rows[p][r]);
#pragma unroll
        for (int p = 0; p < 2; ++p)
#pragma unroll
            for (int r = 0; r < 3; ++r) {
                Q[p][r] = make_float2(0.0f, 0.0f);
                if (nq_[p]) Q[p][r] = __ldg((const float2*)(rows[p][r] + 4));
            }

#pragma unroll
        for (int p = 0; p < 2; ++p) {
            const bool d2 = d2_[p], d1 = d1_[p], lo = lo_[p], hi = hi_[p];
            const float C = C_[p];
            float pv[9];
#pragma unroll
            for (int r = 0; r < 3; ++r) {
                float g0 = d2 ? P[p][r].z : P[p][r].x;
                float g1 = d2 ? P[p][r].w : P[p][r].y;
                float g2 = d2 ? Q[p][r].x : P[p][r].z;
                float g3 = d2 ? Q[p][r].y : P[p][r].w;
                float t0 = d1 ? g1 : g0;
                float t1 = d1 ? g2 : g1;
                float t2 = d1 ? g3 : g2;
                float vl = hi ? t1 : t0;
                float vm = lo ? t0 : (hi ? t2 : t1);
                float vr = lo ? t1 : t2;
                pv[3 * r + 0] = pval(vl, C, Kc);
                pv[3 * r + 1] = pval(vm, C, Kc);
                pv[3 * r + 2] = pval(vr, C, Kc);
            }
            acc[p] = quad_sum(pv[0], pv[1], pv[2], pv[3])
                   + quad_sum(pv[4], pv[5], pv[6], pv[7])
                   + rcpf(pv[8]);
        }
    } else {
        // ---- generic path: scalar gathers, rolled to keep reg pressure low ----
        for (int p = 0; p < 2; ++p) {
            const int idx = idx0 + p;
            if (p == 1 && !has2) break;
            const int b = b0v + (idx >= lim);
            const int x = xs[p], y = ys[p];
            const int xm = max(x - 1, 0), xp = min(x + 1, S - 1);
            const int ym = max(y - 1, 0), yp = min(y + 1, S - 1);
            const float* zb = zbuf + (size_t)b * (size_t)SS;
            const float C = C_[p];
            float a = 0.0f;
            int yy[3] = {ym, y, yp};
            for (int r = 0; r < 3; ++r) {
                const float* rr = zb + (size_t)(unsigned)yy[r] * (unsigned)S;
                a += rcpf(pval(__ldg(rr + xm), C, Kc));
                a += rcpf(pval(__ldg(rr + x ), C, Kc));
                a += rcpf(pval(__ldg(rr + xp), C, Kc));
            }
            acc[p] = a;
        }
    }

    if (has2) {
        float2 o = make_float2(acc[0] * (1.0f / 9.0f), acc[1] * (1.0f / 9.0f));
        __stcs((float2*)(out + idx0), o);     // write-once, evict-first
    } else {
        __stcs(out + idx0, acc[0] * (1.0f / 9.0f));
    }
}

extern "C" void kernel_launch(void* const* d_in, const int* in_sizes, int n_in,
                              void* d_out, int out_size) {
    const float* zbuf   = (const float*)d_in[0];
    const float* depth  = (const float*)d_in[1];
    const int*   xy     = (const int*)  d_in[2];
    const int*   imsz   = (const int*)  d_in[3];
    float*       out    = (float*)d_out;

    const int total      = in_sizes[1];
    const int zbuf_total = in_sizes[0];

    const int threads = 256;
    const int pairs   = (total + 1) / 2;
    const int blocks  = (pairs + threads - 1) / threads;
    shadow_pcf2_kernel<<<blocks, threads>>>(zbuf, depth, xy, imsz, out,
                                            total, zbuf_total);
}